// round 7
// baseline (speedup 1.0000x reference)
#include <cuda_runtime.h>
#include <cuda_bf16.h>

// QueryAndGroup: ball query (first-K ascending in-radius indices) + feature grouping.
// Shapes fixed by the problem: B=4, N=16384, S=4096, C=64, K=64, radius=0.2.
// Output: (B, 3+C, S, K) float32.
//
// Fused single kernel, warp-per-query:
//   phase 1: warp cooperatively scans points in ascending index order, ballot +
//            prefix-popc compaction into shared idx[K], early exit at K hits.
//   phase 2: each lane writes k={2*lane, 2*lane+1} for all 67 channels (float2 stores).
//
// Numerics matched to the reference lowering:
//   qp   : cublas K=3 sgemm serial FMA accumulation, ascending k, acc init 0:
//          fma(qz,pz, fma(qy,py, mul(qx,px)))
//   q2,p2: XLA-GPU multi-row warp reduction (shfl.down tree, identity-0 pad):
//          lanes {x2,y2,z2,0} -> (x2 + z2) + y2, each square rounded:
//          add(add(mul(x,x), mul(z,z)), mul(y,y))
//   d2   : fsub(fadd(q2, p2), fmul(2, qp))  (2*qp exact; fma-contraction of this
//          step is bit-identical)
// Explicit intrinsics prevent nvcc from re-contracting any of it differently.

namespace {
constexpr int B = 4;
constexpr int N = 16384;
constexpr int S = 4096;
constexpr int C = 64;
constexpr int K = 64;          // nsample
constexpr float R2 = 0.04f;    // f32(0.2*0.2) == 0.04f
constexpr int WARPS_PER_BLOCK = 8;
constexpr int THREADS = WARPS_PER_BLOCK * 32;
}

__global__ __launch_bounds__(THREADS)
void query_and_group_kernel(const float* __restrict__ xyz,      // (B, N, 3)
                            const float* __restrict__ new_xyz,  // (B, S, 3)
                            const float* __restrict__ feat,     // (B, C, N)
                            float* __restrict__ out)            // (B, 3+C, S, K)
{
    __shared__ int s_idx[WARPS_PER_BLOCK][K];

    const int warp = threadIdx.x >> 5;
    const int lane = threadIdx.x & 31;
    const int q = blockIdx.x * WARPS_PER_BLOCK + warp;   // global query id
    if (q >= B * S) return;
    const int b = q / S;
    const int s = q - b * S;

    // Query point (broadcast load)
    const float* qp_ptr = new_xyz + ((size_t)b * S + s) * 3;
    const float qx = qp_ptr[0], qy = qp_ptr[1], qz = qp_ptr[2];
    // q2: warp-shuffle reduction order: (x^2 + z^2) + y^2
    const float q2 = __fadd_rn(__fadd_rn(__fmul_rn(qx, qx), __fmul_rn(qz, qz)),
                               __fmul_rn(qy, qy));

    const float* xb = xyz + (size_t)b * N * 3;

    // ---- Phase 1: ball query (first K ascending in-radius indices) ----
    int count = 0;
    for (int base = 0; base < N; base += 32) {
        const int n = base + lane;
        const float px = xb[3 * n + 0];
        const float py = xb[3 * n + 1];
        const float pz = xb[3 * n + 2];
        // p2: warp-shuffle reduction order: (x^2 + z^2) + y^2
        const float p2 = __fadd_rn(__fadd_rn(__fmul_rn(px, px), __fmul_rn(pz, pz)),
                                   __fmul_rn(py, py));
        // qp: sgemm serial FMA accumulation, ascending k
        const float qpd = __fmaf_rn(qz, pz, __fmaf_rn(qy, py, __fmul_rn(qx, px)));
        // d2 = (q2 + p2) - 2*qp
        const float d2 = __fsub_rn(__fadd_rn(q2, p2), __fmul_rn(2.0f, qpd));
        const bool hit = d2 < R2;
        const unsigned m = __ballot_sync(0xffffffffu, hit);
        if (hit) {
            const int pos = count + __popc(m & ((1u << lane) - 1u));
            if (pos < K) s_idx[warp][pos] = n;
        }
        count += __popc(m);
        if (count >= K) break;
    }
    __syncwarp();

    const int k0 = 2 * lane;        // this lane owns output slots k0, k0+1
    const int cnt = (count < K) ? count : K;
    const int fill = (cnt > 0) ? s_idx[warp][0] : 0;
    // pad unfilled slots with first index (or 0 if no neighbor)
    if (k0 >= cnt)     s_idx[warp][k0]     = fill;
    if (k0 + 1 >= cnt) s_idx[warp][k0 + 1] = fill;
    __syncwarp();

    // ---- Phase 2: grouping ----
    const int i0 = s_idx[warp][k0];
    const int i1 = s_idx[warp][k0 + 1];

    const size_t chan_stride = (size_t)S * K;
    float* ob = out + (size_t)b * (3 + C) * chan_stride + (size_t)s * K + k0;

    // grouped_xyz = xyz[idx] - new_xyz (channels 0..2)
    {
        const float x0 = xb[3 * i0 + 0], y0 = xb[3 * i0 + 1], z0 = xb[3 * i0 + 2];
        const float x1 = xb[3 * i1 + 0], y1 = xb[3 * i1 + 1], z1 = xb[3 * i1 + 2];
        *reinterpret_cast<float2*>(ob + 0 * chan_stride) =
            make_float2(__fsub_rn(x0, qx), __fsub_rn(x1, qx));
        *reinterpret_cast<float2*>(ob + 1 * chan_stride) =
            make_float2(__fsub_rn(y0, qy), __fsub_rn(y1, qy));
        *reinterpret_cast<float2*>(ob + 2 * chan_stride) =
            make_float2(__fsub_rn(z0, qz), __fsub_rn(z1, qz));
    }

    // grouped_features (channels 3..66): gathers hit the L2-resident prefix
    const float* fb = feat + (size_t)b * C * N;
    float* of = ob + 3 * chan_stride;
#pragma unroll 8
    for (int c = 0; c < C; ++c) {
        const float f0 = __ldg(fb + (size_t)c * N + i0);
        const float f1 = __ldg(fb + (size_t)c * N + i1);
        *reinterpret_cast<float2*>(of + (size_t)c * chan_stride) = make_float2(f0, f1);
    }
}

extern "C" void kernel_launch(void* const* d_in, const int* in_sizes, int n_in,
                              void* d_out, int out_size)
{
    const float* xyz     = (const float*)d_in[0];  // B*N*3
    const float* new_xyz = (const float*)d_in[1];  // B*S*3
    const float* feat    = (const float*)d_in[2];  // B*C*N
    float* out           = (float*)d_out;          // B*(3+C)*S*K

    const int total_queries = B * S;
    const int grid = (total_queries + WARPS_PER_BLOCK - 1) / WARPS_PER_BLOCK;
    query_and_group_kernel<<<grid, THREADS>>>(xyz, new_xyz, feat, out);
}

// round 8
// speedup vs baseline: 1.0064x; 1.0064x over previous
#include <cuda_runtime.h>
#include <cuda_bf16.h>

// QueryAndGroup, two-kernel version.
// k1: ball query (bit-exact d2 recipe, DO NOT TOUCH) -> idx scratch + xyz channels.
// k2: feature grouping tiled (b, 8-channel, 256-query) for L1 gather locality.
// Shapes: B=4, N=16384, S=4096, C=64, K=64, radius=0.2. Out: (B, 67, S, K) f32.

namespace {
constexpr int B = 4;
constexpr int N = 16384;
constexpr int S = 4096;
constexpr int C = 64;
constexpr int K = 64;          // nsample
constexpr float R2 = 0.04f;
constexpr int WARPS_PER_BLOCK = 8;
constexpr int THREADS = WARPS_PER_BLOCK * 32;

constexpr int CTILE = 8;       // channels per k2 block
constexpr int STILE = 256;     // queries per k2 block
constexpr int P2_THREADS = 256;
}

// idx scratch: 4*4096*64 int32 = 4 MB (static device memory; stays L2-resident
// between the two launches).
__device__ int g_idx[B * S * K];

// ---------------------------------------------------------------------------
// Kernel 1: ball query + xyz channels + idx write.  Phase-1 math is the
// bit-exact recipe from R7 (rel_err == 0.0): qp ascending FMA chain,
// q2/p2 shuffle-tree (x^2+z^2)+y^2, d2 = (q2+p2) - 2*qp.
// ---------------------------------------------------------------------------
__global__ __launch_bounds__(THREADS)
void ball_query_kernel(const float* __restrict__ xyz,      // (B, N, 3)
                       const float* __restrict__ new_xyz,  // (B, S, 3)
                       float* __restrict__ out)            // (B, 3+C, S, K)
{
    __shared__ int s_idx[WARPS_PER_BLOCK][K];

    const int warp = threadIdx.x >> 5;
    const int lane = threadIdx.x & 31;
    const int q = blockIdx.x * WARPS_PER_BLOCK + warp;
    if (q >= B * S) return;
    const int b = q / S;
    const int s = q - b * S;

    const float* qp_ptr = new_xyz + ((size_t)b * S + s) * 3;
    const float qx = qp_ptr[0], qy = qp_ptr[1], qz = qp_ptr[2];
    const float q2 = __fadd_rn(__fadd_rn(__fmul_rn(qx, qx), __fmul_rn(qz, qz)),
                               __fmul_rn(qy, qy));

    const float* xb = xyz + (size_t)b * N * 3;

    int count = 0;
    for (int base = 0; base < N; base += 32) {
        const int n = base + lane;
        const float px = xb[3 * n + 0];
        const float py = xb[3 * n + 1];
        const float pz = xb[3 * n + 2];
        const float p2 = __fadd_rn(__fadd_rn(__fmul_rn(px, px), __fmul_rn(pz, pz)),
                                   __fmul_rn(py, py));
        const float qpd = __fmaf_rn(qz, pz, __fmaf_rn(qy, py, __fmul_rn(qx, px)));
        const float d2 = __fsub_rn(__fadd_rn(q2, p2), __fmul_rn(2.0f, qpd));
        const bool hit = d2 < R2;
        const unsigned m = __ballot_sync(0xffffffffu, hit);
        if (hit) {
            const int pos = count + __popc(m & ((1u << lane) - 1u));
            if (pos < K) s_idx[warp][pos] = n;
        }
        count += __popc(m);
        if (count >= K) break;
    }
    __syncwarp();

    const int k0 = 2 * lane;
    const int cnt = (count < K) ? count : K;
    const int fill = (cnt > 0) ? s_idx[warp][0] : 0;
    if (k0 >= cnt)     s_idx[warp][k0]     = fill;
    if (k0 + 1 >= cnt) s_idx[warp][k0 + 1] = fill;
    __syncwarp();

    const int i0 = s_idx[warp][k0];
    const int i1 = s_idx[warp][k0 + 1];

    // idx -> scratch (coalesced int2)
    *reinterpret_cast<int2*>(g_idx + (size_t)q * K + k0) = make_int2(i0, i1);

    // grouped_xyz = xyz[idx] - new_xyz (channels 0..2)
    const size_t chan_stride = (size_t)S * K;
    float* ob = out + (size_t)b * (3 + C) * chan_stride + (size_t)s * K + k0;
    {
        const float x0 = xb[3 * i0 + 0], y0 = xb[3 * i0 + 1], z0 = xb[3 * i0 + 2];
        const float x1 = xb[3 * i1 + 0], y1 = xb[3 * i1 + 1], z1 = xb[3 * i1 + 2];
        *reinterpret_cast<float2*>(ob + 0 * chan_stride) =
            make_float2(__fsub_rn(x0, qx), __fsub_rn(x1, qx));
        *reinterpret_cast<float2*>(ob + 1 * chan_stride) =
            make_float2(__fsub_rn(y0, qy), __fsub_rn(y1, qy));
        *reinterpret_cast<float2*>(ob + 2 * chan_stride) =
            make_float2(__fsub_rn(z0, qz), __fsub_rn(z1, qz));
    }
}

// ---------------------------------------------------------------------------
// Kernel 2: grouped features.  Block = (stile of 256 queries) x (ctile of 8
// channels).  Iter-outer / channel-inner: idx loaded once (int4) and reused
// across 8 channels; all threads touch the same 8 channel rows concurrently,
// so the hot prefix (~12 KB/row) is fetched from L2 once per block and served
// from L1 thereafter.
// ---------------------------------------------------------------------------
__global__ __launch_bounds__(P2_THREADS)
void group_feat_kernel(const float* __restrict__ feat,   // (B, C, N)
                       float* __restrict__ out)          // (B, 3+C, S, K)
{
    const int b  = blockIdx.z;
    const int c0 = blockIdx.y * CTILE;
    const int s0 = blockIdx.x * STILE;
    const int t  = threadIdx.x;

    const float* fb = feat + ((size_t)b * C + c0) * N;
    const int*   ib = g_idx + ((size_t)b * S + s0) * K;
    float*       ob = out + ((size_t)b * (3 + C) + 3 + c0) * ((size_t)S * K)
                          + (size_t)s0 * K;

    constexpr int ELEMS = STILE * K;               // 16384 per channel
    constexpr int PER_ITER = P2_THREADS * 4;       // 1024
    constexpr int ITERS = ELEMS / PER_ITER;        // 16

#pragma unroll 2
    for (int j = 0; j < ITERS; ++j) {
        const int flat = j * PER_ITER + t * 4;     // s_local*K + k, int4-aligned
        const int4 iv = *reinterpret_cast<const int4*>(ib + flat);

        float v[CTILE][4];
#pragma unroll
        for (int c = 0; c < CTILE; ++c) {
            const float* fc = fb + (size_t)c * N;
            v[c][0] = __ldg(fc + iv.x);
            v[c][1] = __ldg(fc + iv.y);
            v[c][2] = __ldg(fc + iv.z);
            v[c][3] = __ldg(fc + iv.w);
        }
#pragma unroll
        for (int c = 0; c < CTILE; ++c) {
            *reinterpret_cast<float4*>(ob + (size_t)c * S * K + flat) =
                make_float4(v[c][0], v[c][1], v[c][2], v[c][3]);
        }
    }
}

extern "C" void kernel_launch(void* const* d_in, const int* in_sizes, int n_in,
                              void* d_out, int out_size)
{
    const float* xyz     = (const float*)d_in[0];  // B*N*3
    const float* new_xyz = (const float*)d_in[1];  // B*S*3
    const float* feat    = (const float*)d_in[2];  // B*C*N
    float* out           = (float*)d_out;          // B*(3+C)*S*K

    const int total_queries = B * S;
    const int grid1 = (total_queries + WARPS_PER_BLOCK - 1) / WARPS_PER_BLOCK;
    ball_query_kernel<<<grid1, THREADS>>>(xyz, new_xyz, out);

    dim3 grid2(S / STILE, C / CTILE, B);           // (16, 8, 4) = 512 blocks
    group_feat_kernel<<<grid2, P2_THREADS>>>(feat, out);
}

// round 10
// speedup vs baseline: 2.3635x; 2.3486x over previous
#include <cuda_runtime.h>
#include <cuda_bf16.h>

// QueryAndGroup, four-kernel version (resubmit of R8 design; R9 was an infra
// failure with no measurement).
//   t1: transpose xyz (B,N,3) -> SoA xs/ys/zs           (for vectorized scan)
//   t2: transpose feat (B,C,N) -> feat_T (B,N,C)        (for coalesced gathers)
//   k1: ball query, 128 points/warp-iter, bit-exact d2  -> idx + xyz channels
//   k2: block-per-query grouping: coalesced 256B gathers via feat_T, smem
//       transpose, coalesced float4 channel-major stores.
// Shapes: B=4, N=16384, S=4096, C=64, K=64, radius=0.2. Out: (B, 67, S, K) f32.

namespace {
constexpr int B = 4;
constexpr int N = 16384;
constexpr int S = 4096;
constexpr int C = 64;
constexpr int K = 64;
constexpr float R2 = 0.04f;
constexpr int WARPS_PER_BLOCK = 8;
constexpr int THREADS = WARPS_PER_BLOCK * 32;
}

// Static scratch (no allocations allowed).
__device__ __align__(256) float g_featT[(size_t)B * N * C];   // 16.8 MB
__device__ __align__(16)  float g_xs[B * N];
__device__ __align__(16)  float g_ys[B * N];
__device__ __align__(16)  float g_zs[B * N];
__device__ int g_idx[B * S * K];                              // 4 MB

// Bit-exact d2 recipe (rel_err == 0.0 established R7). DO NOT REORDER.
__device__ __forceinline__ float d2_exact(float qx, float qy, float qz, float q2,
                                          float px, float py, float pz)
{
    const float p2 = __fadd_rn(__fadd_rn(__fmul_rn(px, px), __fmul_rn(pz, pz)),
                               __fmul_rn(py, py));
    const float qpd = __fmaf_rn(qz, pz, __fmaf_rn(qy, py, __fmul_rn(qx, px)));
    return __fsub_rn(__fadd_rn(q2, p2), __fmul_rn(2.0f, qpd));
}

// ---------------------------------------------------------------------------
// t1: xyz (B,N,3) -> SoA
// ---------------------------------------------------------------------------
__global__ void transpose_xyz_kernel(const float* __restrict__ xyz)
{
    const int i = blockIdx.x * blockDim.x + threadIdx.x;   // b*N + n
    if (i >= B * N) return;
    const float* p = xyz + (size_t)i * 3;
    g_xs[i] = p[0];
    g_ys[i] = p[1];
    g_zs[i] = p[2];
}

// ---------------------------------------------------------------------------
// t2: feat (B,C,N) -> feat_T (B,N,C), tiled smem transpose
// ---------------------------------------------------------------------------
__global__ void transpose_feat_kernel(const float* __restrict__ feat)
{
    __shared__ float tile[32][33];
    const int b  = blockIdx.z;
    const int n0 = blockIdx.x * 32;
    const int c0 = blockIdx.y * 32;
    const int tx = threadIdx.x;      // 0..31
    const int ty = threadIdx.y;      // 0..7

    const float* fb = feat + (size_t)b * C * N;
#pragma unroll
    for (int i = 0; i < 32; i += 8)
        tile[ty + i][tx] = fb[(size_t)(c0 + ty + i) * N + n0 + tx];
    __syncthreads();

    float* fo = g_featT + (size_t)b * N * C;
#pragma unroll
    for (int i = 0; i < 32; i += 8)
        fo[(size_t)(n0 + ty + i) * C + c0 + tx] = tile[tx][ty + i];
}

// ---------------------------------------------------------------------------
// k1: ball query. Warp per query, 128 points per iteration (4/lane, lane-major
// so global ascending order = (lane, j) lexicographic). Exact first-K via
// 4 ballots + prefix popc. d2 math identical to the verified recipe.
// ---------------------------------------------------------------------------
__global__ __launch_bounds__(THREADS)
void ball_query_kernel(const float* __restrict__ xyz,      // (B, N, 3)
                       const float* __restrict__ new_xyz,  // (B, S, 3)
                       float* __restrict__ out)            // (B, 3+C, S, K)
{
    __shared__ int s_idx[WARPS_PER_BLOCK][K];

    const int warp = threadIdx.x >> 5;
    const int lane = threadIdx.x & 31;
    const int q = blockIdx.x * WARPS_PER_BLOCK + warp;
    if (q >= B * S) return;
    const int b = q / S;
    const int s = q - b * S;

    const float* qp_ptr = new_xyz + ((size_t)b * S + s) * 3;
    const float qx = qp_ptr[0], qy = qp_ptr[1], qz = qp_ptr[2];
    // q2: warp-shuffle reduction order (x^2 + z^2) + y^2  (verified recipe)
    const float q2 = __fadd_rn(__fadd_rn(__fmul_rn(qx, qx), __fmul_rn(qz, qz)),
                               __fmul_rn(qy, qy));

    const float4* xs4 = (const float4*)(g_xs + b * N);
    const float4* ys4 = (const float4*)(g_ys + b * N);
    const float4* zs4 = (const float4*)(g_zs + b * N);

    int count = 0;
    for (int base = 0; base < N; base += 128) {
        const int v = (base >> 2) + lane;
        const float4 X = xs4[v];
        const float4 Y = ys4[v];
        const float4 Z = zs4[v];

        const bool h0 = d2_exact(qx, qy, qz, q2, X.x, Y.x, Z.x) < R2;
        const bool h1 = d2_exact(qx, qy, qz, q2, X.y, Y.y, Z.y) < R2;
        const bool h2 = d2_exact(qx, qy, qz, q2, X.z, Y.z, Z.z) < R2;
        const bool h3 = d2_exact(qx, qy, qz, q2, X.w, Y.w, Z.w) < R2;

        const unsigned m0 = __ballot_sync(0xffffffffu, h0);
        const unsigned m1 = __ballot_sync(0xffffffffu, h1);
        const unsigned m2 = __ballot_sync(0xffffffffu, h2);
        const unsigned m3 = __ballot_sync(0xffffffffu, h3);

        const unsigned below = (1u << lane) - 1u;
        int p = count + __popc(m0 & below) + __popc(m1 & below)
                      + __popc(m2 & below) + __popc(m3 & below);
        const int n0 = base + 4 * lane;
        if (h0 && p < K) s_idx[warp][p] = n0;
        p += h0;
        if (h1 && p < K) s_idx[warp][p] = n0 + 1;
        p += h1;
        if (h2 && p < K) s_idx[warp][p] = n0 + 2;
        p += h2;
        if (h3 && p < K) s_idx[warp][p] = n0 + 3;

        count += __popc(m0) + __popc(m1) + __popc(m2) + __popc(m3);
        if (count >= K) break;
    }
    __syncwarp();

    const int k0 = 2 * lane;
    const int cnt = (count < K) ? count : K;
    const int fill = (cnt > 0) ? s_idx[warp][0] : 0;
    if (k0 >= cnt)     s_idx[warp][k0]     = fill;
    if (k0 + 1 >= cnt) s_idx[warp][k0 + 1] = fill;
    __syncwarp();

    const int i0 = s_idx[warp][k0];
    const int i1 = s_idx[warp][k0 + 1];

    *reinterpret_cast<int2*>(g_idx + (size_t)q * K + k0) = make_int2(i0, i1);

    // grouped_xyz = xyz[idx] - new_xyz (channels 0..2)
    const float* xb = xyz + (size_t)b * N * 3;
    const size_t chan_stride = (size_t)S * K;
    float* ob = out + (size_t)b * (3 + C) * chan_stride + (size_t)s * K + k0;
    {
        const float x0 = xb[3 * i0 + 0], y0 = xb[3 * i0 + 1], z0 = xb[3 * i0 + 2];
        const float x1 = xb[3 * i1 + 0], y1 = xb[3 * i1 + 1], z1 = xb[3 * i1 + 2];
        *reinterpret_cast<float2*>(ob + 0 * chan_stride) =
            make_float2(__fsub_rn(x0, qx), __fsub_rn(x1, qx));
        *reinterpret_cast<float2*>(ob + 1 * chan_stride) =
            make_float2(__fsub_rn(y0, qy), __fsub_rn(y1, qy));
        *reinterpret_cast<float2*>(ob + 2 * chan_stride) =
            make_float2(__fsub_rn(z0, qz), __fsub_rn(z1, qz));
    }
}

// ---------------------------------------------------------------------------
// k2: grouping. Block = one query (128 threads). Gather 64 indices x 256B
// (coalesced: 16 lanes per index, LDG.128), stage transposed in smem
// [k][c] with +1 padding, then write channel-major float4 coalesced.
// ---------------------------------------------------------------------------
__global__ __launch_bounds__(128)
void group_feat_kernel(float* __restrict__ out)
{
    __shared__ int   sidx[K];
    __shared__ float sdata[K][C + 1];   // 64 x 65 floats, pad kills bank conflicts

    const int q = blockIdx.x;
    const int b = q / S;
    const int s = q - b * S;
    const int t = threadIdx.x;

    if (t < 16)
        *reinterpret_cast<int4*>(sidx + t * 4) =
            *reinterpret_cast<const int4*>(g_idx + (size_t)q * K + t * 4);
    __syncthreads();

    const float* ft = g_featT + (size_t)b * N * C;

    // Gather phase: 1024 float4 slots (64 idx x 16 parts), 8 per thread.
#pragma unroll
    for (int jj = 0; jj < 8; ++jj) {
        const int slot = jj * 128 + t;
        const int k    = slot >> 4;
        const int part = slot & 15;
        const int idx  = sidx[k];
        const float4 v = *reinterpret_cast<const float4*>(ft + (size_t)idx * C + part * 4);
        float* d = &sdata[k][part * 4];
        d[0] = v.x; d[1] = v.y; d[2] = v.z; d[3] = v.w;
    }
    __syncthreads();

    // Write phase: out[b][3+c][s][k], 1024 float4 slots (64 c x 16 k-parts).
    float* ob = out + ((size_t)b * (3 + C) + 3) * ((size_t)S * K) + (size_t)s * K;
#pragma unroll
    for (int jj = 0; jj < 8; ++jj) {
        const int slot = jj * 128 + t;
        const int c    = slot >> 4;
        const int kp   = (slot & 15) * 4;
        const float4 v = make_float4(sdata[kp + 0][c], sdata[kp + 1][c],
                                     sdata[kp + 2][c], sdata[kp + 3][c]);
        *reinterpret_cast<float4*>(ob + (size_t)c * (S * K) + kp) = v;
    }
}

extern "C" void kernel_launch(void* const* d_in, const int* in_sizes, int n_in,
                              void* d_out, int out_size)
{
    const float* xyz     = (const float*)d_in[0];  // B*N*3
    const float* new_xyz = (const float*)d_in[1];  // B*S*3
    const float* feat    = (const float*)d_in[2];  // B*C*N
    float* out           = (float*)d_out;          // B*(3+C)*S*K

    transpose_xyz_kernel<<<(B * N + 255) / 256, 256>>>(xyz);

    dim3 tg(N / 32, C / 32, B);                    // (512, 2, 4)
    transpose_feat_kernel<<<tg, dim3(32, 8)>>>(feat);

    const int grid1 = (B * S + WARPS_PER_BLOCK - 1) / WARPS_PER_BLOCK;
    ball_query_kernel<<<grid1, THREADS>>>(xyz, new_xyz, out);

    group_feat_kernel<<<B * S, 128>>>(out);
}